// round 15
// baseline (speedup 1.0000x reference)
#include <cuda_runtime.h>

#define D_DIM 2048
#define TPB   512
#define EPT   8      // 2 rows per block: warps 0-7 row A, warps 8-15 row B

__global__ __launch_bounds__(TPB, 4)
void mxint_softmax_kernel(const float* __restrict__ x, float* __restrict__ out)
{
    const int tid   = threadIdx.x;
    const int lane  = tid & 31;
    const int warp  = tid >> 5;          // 0..15
    const int rowid = warp >> 3;         // 0 or 1
    const int wr    = warp & 7;          // warp index within row
    const int rtid  = tid & 255;         // thread index within row

    const size_t row = (size_t)blockIdx.x * 2 + rowid;
    const float* xr   = x   + row * D_DIM + rtid * EPT;
    float*       orow = out + row * D_DIM + rtid * EPT;

    __shared__ int   s_acc[96];      // per row: 48 (buckets at +16, zero aprons)
    __shared__ int   s_warpmax[16];
    __shared__ int   s_ms7[64];      // per row: 32 packed (s7<<8)|mu
    __shared__ float s_res[1024];    // per row: 512, keyed by pe

    // Issue loads early
    float4 v0 = *(const float4*)(xr);
    float4 v1 = *(const float4*)(xr + 4);

    // Per-lane LUT register: lut[lane] = clip(rne(2^(lane/32) * 64), 127).
    // exp2f err (~2 ulp) is ~1000x below min distance (0.0097) to .5 boundary.
    int lutreg  = min(127, (int)rintf(exp2f(fmaf((float)lane, 0.03125f, 6.0f))));
    int lutreg4 = lutreg << 4;       // mexp*16 for the bucket sum

    if (tid < 96) s_acc[tid] = 0;

    float xs[EPT] = {v0.x, v0.y, v0.z, v0.w, v1.x, v1.y, v1.z, v1.w};

    const float MAGIC = 12582912.0f;         // 1.5 * 2^23
    int pe8[EPT];

    #pragma unroll
    for (int k = 0; k < EPT; k++) {
        float xv = xs[k];
        int bits = __float_as_int(xv);
        // u = biased exp of e1 = ceil(log2|x|): (2*abits-2)>>24 == (abits-1)>>23
        // (unsigned; sign bit falls off the left shift). Clamp makes e1 >= -8.
        // abits==0 gives u=254, harmless: m1f==0 forces pe=256 identically.
        // The float32 log2 rounding quirk (m23 in {1,2}) provably never
        // changes t (both variants saturate / floor identically).
        int u = max((int)((((unsigned)bits << 1) - 2u) >> 24), 118);
        // m1 = clip(rne(x * 2^(7-e1)), -128, 127) via magic-constant rne
        // (exact incl. ties-to-even: |x*2^(7-e1)| <= 128 << 2^22, C even).
        float s = __int_as_float((int)(0x82000000u - ((unsigned)u << 23)));
        float m1f = fmaf(xv, s, MAGIC) - MAGIC;
        m1f = fminf(m1f, 127.0f);            // -128 only at exact powers: legal
        // pe = clip(floor(m1*46*2^(e1-7)) + 256, 0, 511); +256 folded into the
        // fma (exact: 13-bit int * pow2, ulp >= 2^-15, |sum| < 512).  Lower
        // clamp free: F2I.U32.RD saturates negatives to 0.
        float c2 = __int_as_float((int)(((unsigned)u << 23) + 0xFFB80000u));
        unsigned pu = __float2uint_rd(fmaf(m1f, c2, 256.0f));
        pe8[k] = (int)min(pu, 511u);         // pe = (e+8)*32 + idx
    }
    // Tree max (shorter dep chain than serial)
    int run = max(max(max(pe8[0], pe8[1]), max(pe8[2], pe8[3])),
                  max(max(pe8[4], pe8[5]), max(pe8[6], pe8[7])));

    // Per-row inclusive prefix max of pe over thread order (pe lex (e,idx),
    // so (prefix-max pe)>>5 == prefix-max of e').
    int inc = run;
    #pragma unroll
    for (int o = 1; o < 32; o <<= 1) {
        int v = __shfl_up_sync(0xffffffffu, inc, o);
        if (lane >= o) inc = max(inc, v);
    }
    int excl = __shfl_up_sync(0xffffffffu, inc, 1);
    if (lane == 0) excl = 0;
    if (lane == 31) s_warpmax[warp] = inc;
    __syncthreads();                         // bar1 (orders s_acc init too)

    int base = excl, bmaxpe = 0;
    const int wbase = rowid << 3;
    #pragma unroll
    for (int w = 0; w < 8; w++) {
        int wm = s_warpmax[wbase + w];
        if (w < wr) base = max(base, wm);
        bmaxpe = max(bmaxpe, wm);
    }

    // Bucket by plateau value E (prefix max of e'). Bit-exact vs the sequential
    // scan: within a plateau adds are exact per-element floors; cross-plateau
    // shifts compose.  SHFL-based lookup (LDS-gather variant measured slower).
    // Fast path: if a lane's prefix base dominates all its elements, its
    // plateau is the constant E = base>>5.
    int* rowacc = s_acc + rowid * 48;
    bool fastp = ((base >> 5) >= (run >> 5));
    if (__ballot_sync(0xffffffffu, fastp) == 0xffffffffu) {
        const int E = base >> 5;             // per-lane constant plateau
        int acc = 0;
        #pragma unroll
        for (int k = 0; k < EPT; k++) {
            int pe = pe8[k];
            // me16 >> (E - e') == (me16 << e') >> E  (me16<<15 < 2^26, exact)
            int ms = __shfl_sync(0xffffffffu, lutreg4, pe);  // srcLane mod 32
            acc += (ms << (pe >> 5)) >> E;
        }
        // Warp-aggregate when E is warp-uniform (common): 1 ATOMS instead of
        // 32 same-address ATOMS (32 cyc/warp on the MIO pipe).
        int E0 = __shfl_sync(0xffffffffu, E, 0);
        if (__all_sync(0xffffffffu, E == E0)) {
            int sred = __reduce_add_sync(0xffffffffu, acc);
            if (lane == 0) atomicAdd(&rowacc[E0 + 16], sred);
        } else {
            atomicAdd(&rowacc[E + 16], acc);
        }
    } else {
        int run2 = base, curE = -1, acc = 0;
        #pragma unroll
        for (int k = 0; k < EPT; k++) {
            int pe = pe8[k];
            run2 = max(run2, pe);
            int Ee = run2 >> 5;
            int ms = __shfl_sync(0xffffffffu, lutreg4, pe);
            int c  = (ms << (pe >> 5)) >> Ee;
            if (Ee != curE) {
                if (k) atomicAdd(&rowacc[curE + 16], acc);
                curE = Ee; acc = 0;
            }
            acc += c;
        }
        atomicAdd(&rowacc[curE + 16], acc);
    }
    __syncthreads();                         // bar2

    // One warp per row (warp 0 / warp 8): the 16-step serial combine equals
    // its closed form accv = (Sum_k bp[k] << k) >> 15 (halving-floor
    // recurrence composes to one floor) — evaluated DATA-PARALLEL: lane l<16
    // loads one bucket, weights 2^l in u64 (<=2^38), hi/lo-split REDUX
    // (slo < 2^20, shi < 2^23), recombined in u64, one shift.  Then per-idx
    // division: lane i owns LUT index i (mexp already in lutreg).
    if (wr == 0) {
        int idx = (bmaxpe >> 5) + 1 + lane;          // window [top-15 .. top]
        unsigned long long t = (lane < 16)
            ? ((unsigned long long)(unsigned)rowacc[idx]) << lane : 0ULL;
        unsigned slo = __reduce_add_sync(0xffffffffu, (unsigned)(t & 0xFFFFu));
        unsigned shi = __reduce_add_sync(0xffffffffu, (unsigned)(t >> 16));
        unsigned accv = (unsigned)(((((unsigned long long)shi) << 16) + slo) >> 15);
        // IEEE f32 divide + floorf replicates the reference's float path
        // (accv < 2^24 exact in f32). moi in [0,31].
        int moi = (int)floorf((float)(lutreg << 8) / (float)accv);
        int cl2 = (moi <= 1) ? 0 : (32 - __clz(moi - 1));
        int s7  = 7 - cl2;
        int mu  = min(127, moi << s7);       // reference's clipped mantissa
        s_ms7[rowid * 32 + lane] = (s7 << 8) | mu;
    }
    __syncthreads();                         // bar3

    // Build this row's 512-entry result table: entry j=(e'<<5)|idx is the
    // re-quantized output.  Exact closed form (R3-proven, incl. pow2 128->127
    // clip and e2=-8 underflow with rne ties-to-even):
    //   d = e' + (3-bmax) - s7;  r = rne(mu*2^min(0,d)) * 2^(max(0,d)-15)
    {
        const int C = 11 - (bmaxpe >> 5);    // 3 - bmax, bmax = (bmaxpe>>5)-8
        float* rowres = s_res + rowid * 512;
        const int* rowms = s_ms7 + rowid * 32;
        #pragma unroll
        for (int jj = 0; jj < 2; jj++) {
            int j  = rtid + jj * 256;        // j & 31 == lane
            int w  = rowms[lane];
            int d  = (j >> 5) + C - (w >> 8);
            int dn = min(d, 0);
            int dp = d - dn;
            float m2 = rintf((float)(w & 255) * __int_as_float((dn + 127) << 23));
            rowres[j] = m2 * __int_as_float((dp + 112) << 23);  // * 2^(dp-15)
        }
    }
    __syncthreads();                         // bar4

    // Epilogue: one shared load per element.
    const float* rowres = s_res + rowid * 512;
    float r[EPT];
    #pragma unroll
    for (int k = 0; k < EPT; k++) r[k] = rowres[pe8[k]];
    *(float4*)(orow)     = make_float4(r[0], r[1], r[2], r[3]);
    *(float4*)(orow + 4) = make_float4(r[4], r[5], r[6], r[7]);
}

extern "C" void kernel_launch(void* const* d_in, const int* in_sizes, int n_in,
                              void* d_out, int out_size)
{
    const float* x = (const float*)d_in[0];
    float* out = (float*)d_out;
    int rows = in_sizes[0] / D_DIM;
    mxint_softmax_kernel<<<rows / 2, TPB>>>(x, out);
}

// round 16
// speedup vs baseline: 1.1848x; 1.1848x over previous
#include <cuda_runtime.h>

#define D_DIM 2048
#define TPB   256
#define EPT   8      // 256*8 = 2048 = one row per block

__global__ __launch_bounds__(TPB, 8)
void mxint_softmax_kernel(const float* __restrict__ x, float* __restrict__ out)
{
    const int tid  = threadIdx.x;
    const int lane = tid & 31;
    const int warp = tid >> 5;

    const float* xr   = x   + (size_t)blockIdx.x * D_DIM + tid * EPT;
    float*       orow = out + (size_t)blockIdx.x * D_DIM + tid * EPT;

    __shared__ int   s_acc[48];      // buckets [16..31] (e'+16), zero aprons both sides
    __shared__ int   s_warpmax[8];
    __shared__ int   s_ms7[32];      // per-idx packed (s7<<8)|mu
    __shared__ float s_res[512];     // final result keyed by pe

    // Issue loads early
    float4 v0 = *(const float4*)(xr);
    float4 v1 = *(const float4*)(xr + 4);

    // Per-lane LUT register: lut[lane] = clip(rne(2^(lane/32) * 64), 127).
    // exp2f err (~2 ulp) is ~1000x below min distance (0.0097) to .5 boundary.
    int lutreg  = min(127, (int)rintf(exp2f(fmaf((float)lane, 0.03125f, 6.0f))));
    int lutreg4 = lutreg << 4;       // mexp*16 for the bucket sum

    if (tid < 48) s_acc[tid] = 0;

    float xs[EPT] = {v0.x, v0.y, v0.z, v0.w, v1.x, v1.y, v1.z, v1.w};

    const float MAGIC = 12582912.0f;         // 1.5 * 2^23
    int pe8[EPT];

    #pragma unroll
    for (int k = 0; k < EPT; k++) {
        float xv = xs[k];
        int bits = __float_as_int(xv);
        // u = biased exp of e1 = ceil(log2|x|): (2*abits-2)>>24 == (abits-1)>>23
        // (unsigned; sign bit falls off the left shift). Clamp makes e1 >= -8.
        // abits==0 gives u=254, harmless: m1f==0 forces pe=256 identically.
        // The float32 log2 rounding quirk (m23 in {1,2}) provably never
        // changes t (both variants saturate / floor identically).
        int u = max((int)((((unsigned)bits << 1) - 2u) >> 24), 118);
        // m1 = clip(rne(x * 2^(7-e1)), -128, 127) via magic-constant rne
        // (exact incl. ties-to-even: |x*2^(7-e1)| <= 128 << 2^22, C even).
        float s = __int_as_float((int)(0x82000000u - ((unsigned)u << 23)));
        float m1f = fmaf(xv, s, MAGIC) - MAGIC;
        m1f = fminf(m1f, 127.0f);            // 128 only at exact +pow2: clip
        // pe = clip(floor(m1*46*2^(e1-7)) + 256, 0, 511); +256 folded into the
        // fma (exact: 13-bit int * pow2, ulp >= 2^-15, |sum| < 512).  Lower
        // clamp free: F2I.U32.RD saturates negatives to 0.
        float c2 = __int_as_float((int)(((unsigned)u << 23) + 0xFFB80000u));
        unsigned pu = __float2uint_rd(fmaf(m1f, c2, 256.0f));
        pe8[k] = (int)min(pu, 511u);         // pe = (e+8)*32 + idx
    }
    // Tree max (shorter dep chain than serial)
    int run = max(max(max(pe8[0], pe8[1]), max(pe8[2], pe8[3])),
                  max(max(pe8[4], pe8[5]), max(pe8[6], pe8[7])));

    // Block-wide inclusive prefix max of pe over thread order (pe lex (e,idx),
    // so (prefix-max pe)>>5 == prefix-max of e').
    int inc = run;
    #pragma unroll
    for (int o = 1; o < 32; o <<= 1) {
        int v = __shfl_up_sync(0xffffffffu, inc, o);
        if (lane >= o) inc = max(inc, v);
    }
    int excl = __shfl_up_sync(0xffffffffu, inc, 1);
    if (lane == 0) excl = 0;
    if (lane == 31) s_warpmax[warp] = inc;
    __syncthreads();                         // bar1 (orders s_acc init too)

    // Cross-warp base / block max via REDUX instead of an 8-iteration
    // LDS+IMNMX loop (~30 ops -> ~7).  wm read is conflict-free (8 addrs,
    // 4-lane broadcast groups).
    int wm     = s_warpmax[lane & 7];
    int bmaxpe = __reduce_max_sync(0xffffffffu, wm);
    int basew  = __reduce_max_sync(0xffffffffu, ((lane & 7) < warp) ? wm : 0);
    int base   = max(excl, basew);

    // Bucket by plateau value E (prefix max of e'). Bit-exact vs the sequential
    // scan: within a plateau adds are exact per-element floors; cross-plateau
    // shifts compose.  SHFL-based lookup (LDS-gather variant measured slower).
    // Fast path: if a lane's prefix base dominates all its elements, its
    // plateau is the constant E = base>>5.
    bool fastp = ((base >> 5) >= (run >> 5));
    if (__ballot_sync(0xffffffffu, fastp) == 0xffffffffu) {
        const int E = base >> 5;             // per-lane constant plateau
        int acc = 0;
        #pragma unroll
        for (int k = 0; k < EPT; k++) {
            int pe = pe8[k];
            // me16 >> (E - e') == (me16 << e') >> E  (me16<<15 < 2^26, exact)
            int ms = __shfl_sync(0xffffffffu, lutreg4, pe);  // srcLane mod 32
            acc += (ms << (pe >> 5)) >> E;
        }
        // Warp-aggregate when E is warp-uniform (common): 1 ATOMS instead of
        // 32 same-address ATOMS (32 cyc/warp on the MIO pipe).
        int E0 = __shfl_sync(0xffffffffu, E, 0);
        if (__all_sync(0xffffffffu, E == E0)) {
            int sred = __reduce_add_sync(0xffffffffu, acc);
            if (lane == 0) atomicAdd(&s_acc[E0 + 16], sred);
        } else {
            atomicAdd(&s_acc[E + 16], acc);
        }
    } else {
        int run2 = base, curE = -1, acc = 0;
        #pragma unroll
        for (int k = 0; k < EPT; k++) {
            int pe = pe8[k];
            run2 = max(run2, pe);
            int Ee = run2 >> 5;
            int ms = __shfl_sync(0xffffffffu, lutreg4, pe);
            int c  = (ms << (pe >> 5)) >> Ee;
            if (Ee != curE) {
                if (k) atomicAdd(&s_acc[curE + 16], acc);
                curE = Ee; acc = 0;
            }
            acc += c;
        }
        atomicAdd(&s_acc[curE + 16], acc);
    }
    __syncthreads();                         // bar2

    // Warp 0 only.  The 16-step serial combine (accv = (accv>>1)+bp[k])
    // equals its closed form accv = (Sum_k bp[k] << k) >> 15  (halving-floor
    // recurrence with integer addends composes to one floor) — evaluated
    // DATA-PARALLEL: lane l<16 loads one bucket, weights 2^l in u64 (<=2^38),
    // hi/lo-split REDUX (slo < 2^20, shi < 2^23), recombined in u64, one
    // shift.  Then per-idx division: lane i owns LUT index i.
    if (tid < 32) {
        int idx = (bmaxpe >> 5) + 1 + lane;          // window [top-15 .. top]
        unsigned long long t = (lane < 16)
            ? ((unsigned long long)(unsigned)s_acc[idx]) << lane : 0ULL;
        unsigned slo = __reduce_add_sync(0xffffffffu, (unsigned)(t & 0xFFFFu));
        unsigned shi = __reduce_add_sync(0xffffffffu, (unsigned)(t >> 16));
        unsigned accv = (unsigned)(((((unsigned long long)shi) << 16) + slo) >> 15);
        // IEEE f32 divide + floorf replicates the reference's float path
        // (accv < 2^24 exact in f32). moi in [0,31].
        int moi = (int)floorf((float)(lutreg << 8) / (float)accv);
        int cl2 = (moi <= 1) ? 0 : (32 - __clz(moi - 1));
        int s7  = 7 - cl2;
        int mu  = min(127, moi << s7);       // reference's clipped mantissa
        s_ms7[lane] = (s7 << 8) | mu;
    }
    __syncthreads();                         // bar3

    // Build 512-entry result table: entry j=(e'<<5)|idx = re-quantized output.
    // Exact closed form (R3-proven, incl. pow2 128->127 clip and e2=-8
    // underflow with rne ties-to-even):
    //   d = e' + (3-bmax) - s7;  r = rne(mu*2^min(0,d)) * 2^(max(0,d)-15)
    // Thread tid writes j=tid (e'=warp) and j=tid+256 (e'=warp+8): same lane
    // -> same (s7,mu); hoist the unpack + I2F.
    {
        int   w   = s_ms7[lane];             // conflict-free, lane-indexed
        float muf = (float)(w & 255);
        int d = warp + (11 - (bmaxpe >> 5)) - (w >> 8);   // entry 0
        #pragma unroll
        for (int jj = 0; jj < 2; jj++) {
            int dn = min(d, 0);
            int dp = d - dn;
            float m2 = rintf(muf * __int_as_float((dn + 127) << 23));
            s_res[tid + jj * 256] = m2 * __int_as_float((dp + 112) << 23); // *2^(dp-15)
            d += 8;                          // entry 1: e' += 8
        }
    }
    __syncthreads();                         // bar4

    // Epilogue: one shared load per element.
    float r[EPT];
    #pragma unroll
    for (int k = 0; k < EPT; k++) r[k] = s_res[pe8[k]];
    *(float4*)(orow)     = make_float4(r[0], r[1], r[2], r[3]);
    *(float4*)(orow + 4) = make_float4(r[4], r[5], r[6], r[7]);
}

extern "C" void kernel_launch(void* const* d_in, const int* in_sizes, int n_in,
                              void* d_out, int out_size)
{
    const float* x = (const float*)d_in[0];
    float* out = (float*)d_out;
    int rows = in_sizes[0] / D_DIM;
    mxint_softmax_kernel<<<rows, TPB>>>(x, out);
}